// round 16
// baseline (speedup 1.0000x reference)
#include <cuda_runtime.h>
#include <cuda_fp16.h>
#include <cstdint>

#define NB   8
#define IC   512
#define OC   512
#define PX   4096
#define KTOT 4608
#define NKS3 72            // KTOT / 64
#define STG  3             // pipeline depth

// ---------------- scratch (device globals; no allocation) ----------------
__device__ float g_smod[NB * IC];
__device__ float g_s2[NB * IC];
__device__ float g_sig[NB * OC];
__device__ __half g_A[(size_t)NB * OC * KTOT];       // [b][o][k]  single fp16 plane
// shifted, halo-padded fp16 images: [b][shift 0..2][ci][h_pad 0..65][w 0..63]
__device__ __half g_xsh[(size_t)NB * 3 * IC * 66 * 64];

// ---------------- baseline-PTX helpers (valid on plain sm_103) ----------------
__device__ __forceinline__ void cp16(uint32_t dst, const void* src) {
    asm volatile("cp.async.cg.shared.global [%0], [%1], 16;" :: "r"(dst), "l"(src));
}
__device__ __forceinline__ void cp_commit() {
    asm volatile("cp.async.commit_group;" ::: "memory");
}
__device__ __forceinline__ void cp_wait1() {
    asm volatile("cp.async.wait_group 1;" ::: "memory");
}
__device__ __forceinline__ void ldsm4(uint32_t* r, uint32_t a) {
    asm volatile("ldmatrix.sync.aligned.m8n8.x4.shared.b16 {%0,%1,%2,%3}, [%4];"
                 : "=r"(r[0]), "=r"(r[1]), "=r"(r[2]), "=r"(r[3]) : "r"(a));
}
__device__ __forceinline__ void ldsm4t(uint32_t* r, uint32_t a) {
    asm volatile("ldmatrix.sync.aligned.m8n8.x4.trans.shared.b16 {%0,%1,%2,%3}, [%4];"
                 : "=r"(r[0]), "=r"(r[1]), "=r"(r[2]), "=r"(r[3]) : "r"(a));
}
__device__ __forceinline__ void mma16816(float* c, const uint32_t* a, const uint32_t* b) {
    asm volatile(
        "mma.sync.aligned.m16n8k16.row.col.f32.f16.f16.f32 "
        "{%0,%1,%2,%3},{%4,%5,%6,%7},{%8,%9},{%0,%1,%2,%3};"
        : "+f"(c[0]), "+f"(c[1]), "+f"(c[2]), "+f"(c[3])
        : "r"(a[0]), "r"(a[1]), "r"(a[2]), "r"(a[3]), "r"(b[0]), "r"(b[1]));
}

// ---------------------------------------------------------------------------
// K1: style  s[b,i] = latent.w_lin * C_LIN + b_lin   (warp per output i)
// ---------------------------------------------------------------------------
__global__ void k_style(const float* __restrict__ latent,
                        const float* __restrict__ w_lin,
                        const float* __restrict__ b_lin) {
    __shared__ float lat[512];
    const int b = blockIdx.x;
    const int tid = threadIdx.x, lane = tid & 31;
    lat[tid]       = latent[b * 512 + tid];
    lat[tid + 256] = latent[b * 512 + tid + 256];
    __syncthreads();
    const int i = blockIdx.y * 8 + (tid >> 5);
    const float4* wr = (const float4*)(w_lin + (size_t)i * 512);
    float acc = 0.f;
#pragma unroll
    for (int t = 0; t < 4; ++t) {
        float4 v = __ldg(wr + lane + t * 32);
        int j0 = (lane + t * 32) * 4;
        acc += v.x * lat[j0] + v.y * lat[j0 + 1] + v.z * lat[j0 + 2] + v.w * lat[j0 + 3];
    }
#pragma unroll
    for (int st = 16; st > 0; st >>= 1) acc += __shfl_xor_sync(0xffffffffu, acc, st);
    if (lane == 0) {
        const float C_LIN  = 0.04419417382415922f;   // 1/sqrt(512)
        const float C_CONV = 0.014731391274719742f;  // 1/sqrt(4608)
        float s = acc * C_LIN + b_lin[i];
        g_smod[b * 512 + i] = s * C_CONV;
        g_s2[b * 512 + i]   = s * s;
    }
}

// ---------------------------------------------------------------------------
// K2: fused modulate + sigma, single pass over w_conv (read once, emit 8 b).
// ---------------------------------------------------------------------------
__global__ void k_moda(const float* __restrict__ w_conv) {
    __shared__ float red[8][8];
    const int o = blockIdx.x, tid = threadIdx.x;
    const int lane = tid & 31, wrp = tid >> 5;
    const float* wr = w_conv + (size_t)o * KTOT;
    float accs[8];
#pragma unroll
    for (int b = 0; b < 8; ++b) accs[b] = 0.f;

    for (int g = tid; g < KTOT / 8; g += 256) {
        const int k0 = g * 8;
        float w[8];
        float4 w0 = __ldg((const float4*)(wr + k0));
        float4 w1 = __ldg((const float4*)(wr + k0 + 4));
        w[0] = w0.x; w[1] = w0.y; w[2] = w0.z; w[3] = w0.w;
        w[4] = w1.x; w[5] = w1.y; w[6] = w1.z; w[7] = w1.w;
        __half hv[8][8];                       // [b][e]
#pragma unroll
        for (int e = 0; e < 8; ++e) {
            const int i = (k0 + e) / 9;
            const float w2 = w[e] * w[e];
#pragma unroll
            for (int b = 0; b < 8; ++b) {
                hv[b][e] = __float2half_rn(w[e] * g_smod[b * 512 + i]);
                accs[b] += w2 * g_s2[b * 512 + i];
            }
        }
#pragma unroll
        for (int b = 0; b < 8; ++b)
            *(uint4*)(g_A + ((size_t)(b * OC + o)) * KTOT + k0) = *(const uint4*)hv[b];
    }
#pragma unroll
    for (int st = 16; st > 0; st >>= 1)
#pragma unroll
        for (int b = 0; b < 8; ++b)
            accs[b] += __shfl_xor_sync(0xffffffffu, accs[b], st);
    if (lane == 0)
#pragma unroll
        for (int b = 0; b < 8; ++b) red[b][wrp] = accs[b];
    __syncthreads();
    if (tid < 8) {
        float v = 0.f;
#pragma unroll
        for (int w8 = 0; w8 < 8; ++w8) v += red[tid][w8];
        g_sig[tid * 512 + o] = rsqrtf(v * (1.0f / 4608.0f) + 1e-8f);
    }
}

// ---------------------------------------------------------------------------
// K3: shifted fp16 planes, one block per (ci,b): read x once into a haloed
// smem tile, emit all 3 shifts with uint4 stores.
// ---------------------------------------------------------------------------
__global__ void k_xsh(const float* __restrict__ x) {
    __shared__ float tile[66][68];
    const int ci = blockIdx.x, b = blockIdx.y, tid = threadIdx.x;
    const float* xc = x + ((size_t)(b * IC + ci) << 12);
    for (int i = tid; i < 66 * 34; i += 256)
        *(float2*)(&tile[0][0] + i * 2) = make_float2(0.f, 0.f);
    __syncthreads();
    for (int i = tid; i < 64 * 16; i += 256) {
        const int r = i >> 4, c4 = (i & 15) * 4;
        float4 v = *(const float4*)(xc + (r << 6) + c4);
        tile[r + 1][c4 + 1] = v.x;
        tile[r + 1][c4 + 2] = v.y;
        tile[r + 1][c4 + 3] = v.z;
        tile[r + 1][c4 + 4] = v.w;
    }
    __syncthreads();
    __half* dst0 = g_xsh + (((size_t)b * 3) * IC + ci) * 66 * 64;
    for (int i = tid; i < 3 * 66 * 8; i += 256) {
        const int sh = i / 528;
        const int rem = i - sh * 528;
        const int hp = rem >> 3, c8 = (rem & 7) * 8;
        __half hv[8];
#pragma unroll
        for (int e = 0; e < 8; ++e)
            hv[e] = __float2half_rn(tile[hp][c8 + e + sh]);
        *(uint4*)(dst0 + ((size_t)sh * IC * 66 + hp) * 64 + c8) = *(const uint4*)hv;
    }
}

// ---------------------------------------------------------------------------
// K4: fp16 GEMM, BM=128 x BN=128, BK=64 stages (72 iters), 3-stage pipeline,
// 256 threads / 8 warps, __launch_bounds__(256,2) (reg cap 128 = natural use;
// 512-thr + occ2 -> 64-reg cap catastrophic spills: stays banned).
// A[3][128 rows x 144B] (64 halfs data + 16B pad; 144=9*16 conflict-free)
// B[3][64 k-rows x 272B] (128 halfs + pad)
// Per thread per stage: 4 cp16 (A) + 4 cp16 (B).  wait_group 1.
// ---------------------------------------------------------------------------
#define A_ST   18432               // 128 * 144
#define B_ST   17408               // 64 * 272
#define B_OFF  (STG * A_ST)        // 55,296
#define SMEM_TOTAL (B_OFF + STG * B_ST)   // 107,520

__global__ void __launch_bounds__(256, 2)
k_gemm(const float* __restrict__ b_conv, float* __restrict__ out) {
    extern __shared__ char smem[];
    const uint32_t sb = (uint32_t)__cvta_generic_to_shared(smem);
    const int tid = threadIdx.x, wid = tid >> 5, lane = tid & 31;
    const int mt = blockIdx.x, nt = blockIdx.y, b = blockIdx.z;
    const int o0 = mt * 128, p0 = nt * 128;
    const int wm = (wid >> 1) * 32, wn = (wid & 1) * 64;

    // -------- A cp.async: 4 cp16/thread (row = tid>>1, half = tid&1) --------
    const int arow = tid >> 1, ah = tid & 1;
    const __half* asrc = g_A + ((size_t)(b * OC + o0 + arow)) * KTOT + ah * 32;
    const uint32_t adst = sb + (uint32_t)(arow * 144 + ah * 64);

    auto issueA = [&](int s, int buf) {
        const uint32_t d = adst + buf * A_ST;
        const __half* p = asrc + s * 64;
        cp16(d,      p);
        cp16(d + 16, p + 8);
        cp16(d + 32, p + 16);
        cp16(d + 48, p + 24);
    };

    // -------- B cp.async: 4 cp16/thread (k-row = tid>>2, quarter = tid&3) ----
    const int kr = tid >> 2, q = tid & 3;
    const int r0 = nt * 2;
    const __half* xshb = g_xsh + ((size_t)b * 3 * IC) * 66 * 64;
    const uint32_t bdst = sb + B_OFF + (uint32_t)(kr * 272 + q * 64);

    auto issueB = [&](int s, int buf) {
        const int k = s * 64 + kr;
        const int ci = k / 9, t = k - ci * 9;
        const int ty = t / 3, tx = t - ty * 3;
        const __half* src =
            xshb + (((size_t)tx * IC + ci) * 66 + (r0 + ty + (q >> 1))) * 64 +
            (q & 1) * 32;
        const uint32_t d = bdst + buf * B_ST;
        cp16(d,      src);
        cp16(d + 16, src + 8);
        cp16(d + 32, src + 16);
        cp16(d + 48, src + 24);
    };

    // -------- ldmatrix lane offsets --------
    const uint32_t a_lane = (uint32_t)((lane & 15) * 144 + (lane >> 4) * 16);
    const uint32_t b_lane = (uint32_t)((((lane & 7) + ((lane >> 3) & 1) * 8) * 136 +
                                       ((lane >> 4) << 3)) * 2);

    float acc[2][8][4];
#pragma unroll
    for (int mi = 0; mi < 2; ++mi)
#pragma unroll
        for (int j = 0; j < 8; ++j)
#pragma unroll
            for (int q2 = 0; q2 < 4; ++q2) acc[mi][j][q2] = 0.f;

    issueA(0, 0); issueB(0, 0); cp_commit();
    issueA(1, 1); issueB(1, 1); cp_commit();

    int ibuf = 2, cbuf = 0;
#pragma unroll 1
    for (int s = 0; s < NKS3; ++s) {
        cp_wait1();
        __syncthreads();
        if (s + 2 < NKS3) { issueA(s + 2, ibuf); issueB(s + 2, ibuf); }
        cp_commit();
        if (++ibuf == STG) ibuf = 0;

        const uint32_t ab = sb + cbuf * A_ST;
        const uint32_t bb = sb + B_OFF + cbuf * B_ST;
        if (++cbuf == STG) cbuf = 0;

#pragma unroll
        for (int kk = 0; kk < 2; ++kk) {
            uint32_t af[2][2][4];             // [mi][f(k16)]
#pragma unroll
            for (int mi = 0; mi < 2; ++mi) {
                const uint32_t ad = ab + (uint32_t)((wm + mi * 16) * 144) +
                                    a_lane + kk * 64;
                ldsm4(af[mi][0], ad);
                ldsm4(af[mi][1], ad + 32);
            }
            const uint32_t bk = bb + (uint32_t)(kk * 8704);
#pragma unroll
            for (int n2 = 0; n2 < 4; ++n2) {
#pragma unroll
                for (int f = 0; f < 2; ++f) {
                    uint32_t bf[4];
                    ldsm4t(bf, bk + (uint32_t)(f * 4352) +
                               (uint32_t)((wn + n2 * 16) * 2) + b_lane);
#pragma unroll
                    for (int mi = 0; mi < 2; ++mi)
#pragma unroll
                        for (int nf = 0; nf < 2; ++nf)
                            mma16816(acc[mi][n2 * 2 + nf], af[mi][f], &bf[nf * 2]);
                }
            }
        }
    }

    // -------- epilogue: demodulate + bias --------
    const int row_l = lane >> 2, col_l = (lane & 3) * 2;
#pragma unroll
    for (int mi = 0; mi < 2; ++mi) {
        const int oa = o0 + wm + mi * 16 + row_l;
        const int ob = oa + 8;
        const float sa = g_sig[b * OC + oa], ba = b_conv[oa];
        const float sc = g_sig[b * OC + ob], bc = b_conv[ob];
        float* ra = out + (((size_t)(b * OC + oa)) << 12) + p0 + wn + col_l;
        float* rb = out + (((size_t)(b * OC + ob)) << 12) + p0 + wn + col_l;
#pragma unroll
        for (int j = 0; j < 8; ++j) {
            float2 v0, v1;
            v0.x = acc[mi][j][0] * sa + ba;
            v0.y = acc[mi][j][1] * sa + ba;
            v1.x = acc[mi][j][2] * sc + bc;
            v1.y = acc[mi][j][3] * sc + bc;
            *(float2*)(ra + j * 8) = v0;
            *(float2*)(rb + j * 8) = v1;
        }
    }
}

// ---------------------------------------------------------------------------
extern "C" void kernel_launch(void* const* d_in, const int* in_sizes, int n_in,
                              void* d_out, int out_size) {
    const float* x      = (const float*)d_in[0];
    const float* latent = (const float*)d_in[1];
    const float* w_lin  = (const float*)d_in[2];
    const float* b_lin  = (const float*)d_in[3];
    const float* w_conv = (const float*)d_in[4];
    const float* b_conv = (const float*)d_in[5];
    float* out = (float*)d_out;

    cudaFuncSetAttribute(k_gemm, cudaFuncAttributeMaxDynamicSharedMemorySize, SMEM_TOTAL);

    k_style<<<dim3(NB, 64), 256>>>(latent, w_lin, b_lin);
    k_moda<<<OC, 256>>>(w_conv);
    k_xsh<<<dim3(IC, NB), 256>>>(x);
    k_gemm<<<dim3(4, 32, NB), 256, SMEM_TOTAL>>>(b_conv, out);
}

// round 17
// speedup vs baseline: 1.4975x; 1.4975x over previous
#include <cuda_runtime.h>
#include <cuda_fp16.h>
#include <cstdint>

#define NB   8
#define IC   512
#define OC   512
#define PX   4096
#define NT   1024          // winograd tiles per image (32x32)
#define STG  5

// ---------------- scratch (device globals; no allocation) ----------------
__device__ float g_smod[NB * IC];
__device__ float g_s2[NB * IC];
__device__ float g_sig[NB * OC];
__device__ __half g_U[(size_t)NB * 16 * OC * IC];    // [b][xi][o][i]
__device__ __half g_V[(size_t)NB * 16 * IC * NT];    // [b][xi][i][t]
__device__ __half g_M[(size_t)NB * 16 * OC * NT];    // [b][xi][o][t]

// ---------------- baseline-PTX helpers (valid on plain sm_103) ----------------
__device__ __forceinline__ void cp16(uint32_t dst, const void* src) {
    asm volatile("cp.async.cg.shared.global [%0], [%1], 16;" :: "r"(dst), "l"(src));
}
__device__ __forceinline__ void cp_commit() {
    asm volatile("cp.async.commit_group;" ::: "memory");
}
__device__ __forceinline__ void cp_wait3() {
    asm volatile("cp.async.wait_group 3;" ::: "memory");
}
__device__ __forceinline__ void ldsm4(uint32_t* r, uint32_t a) {
    asm volatile("ldmatrix.sync.aligned.m8n8.x4.shared.b16 {%0,%1,%2,%3}, [%4];"
                 : "=r"(r[0]), "=r"(r[1]), "=r"(r[2]), "=r"(r[3]) : "r"(a));
}
__device__ __forceinline__ void ldsm4t(uint32_t* r, uint32_t a) {
    asm volatile("ldmatrix.sync.aligned.m8n8.x4.trans.shared.b16 {%0,%1,%2,%3}, [%4];"
                 : "=r"(r[0]), "=r"(r[1]), "=r"(r[2]), "=r"(r[3]) : "r"(a));
}
__device__ __forceinline__ void mma16816(float* c, const uint32_t* a, const uint32_t* b) {
    asm volatile(
        "mma.sync.aligned.m16n8k16.row.col.f32.f16.f16.f32 "
        "{%0,%1,%2,%3},{%4,%5,%6,%7},{%8,%9},{%0,%1,%2,%3};"
        : "+f"(c[0]), "+f"(c[1]), "+f"(c[2]), "+f"(c[3])
        : "r"(a[0]), "r"(a[1]), "r"(a[2]), "r"(a[3]), "r"(b[0]), "r"(b[1]));
}

// ---------------------------------------------------------------------------
// K1: style  s[b,i] = latent.w_lin * C_LIN + b_lin   (warp per output i)
// ---------------------------------------------------------------------------
__global__ void k_style(const float* __restrict__ latent,
                        const float* __restrict__ w_lin,
                        const float* __restrict__ b_lin) {
    __shared__ float lat[512];
    const int b = blockIdx.x;
    const int tid = threadIdx.x, lane = tid & 31;
    lat[tid]       = latent[b * 512 + tid];
    lat[tid + 256] = latent[b * 512 + tid + 256];
    __syncthreads();
    const int i = blockIdx.y * 8 + (tid >> 5);
    const float4* wr = (const float4*)(w_lin + (size_t)i * 512);
    float acc = 0.f;
#pragma unroll
    for (int t = 0; t < 4; ++t) {
        float4 v = __ldg(wr + lane + t * 32);
        int j0 = (lane + t * 32) * 4;
        acc += v.x * lat[j0] + v.y * lat[j0 + 1] + v.z * lat[j0 + 2] + v.w * lat[j0 + 3];
    }
#pragma unroll
    for (int st = 16; st > 0; st >>= 1) acc += __shfl_xor_sync(0xffffffffu, acc, st);
    if (lane == 0) {
        const float C_LIN  = 0.04419417382415922f;   // 1/sqrt(512)
        const float C_CONV = 0.014731391274719742f;  // 1/sqrt(4608)
        float s = acc * C_LIN + b_lin[i];
        g_smod[b * 512 + i] = s * C_CONV;
        g_s2[b * 512 + i]   = s * s;
    }
}

// ---------------------------------------------------------------------------
// K2: U = G g G^T per (b,o,i)  (modulated, fp16) + fused sigma reduce.
// G = [[1,0,0],[.5,.5,.5],[.5,-.5,.5],[0,0,1]]
// ---------------------------------------------------------------------------
__global__ void k_uprep(const float* __restrict__ w_conv) {
    __shared__ float red[8][8];
    const int o = blockIdx.x, tid = threadIdx.x;
    const int lane = tid & 31, wrp = tid >> 5;
    float accs[8];
#pragma unroll
    for (int b = 0; b < 8; ++b) accs[b] = 0.f;

    for (int i = tid; i < IC; i += 256) {
        float w[9];
        const float* wp = w_conv + ((size_t)o * IC + i) * 9;
#pragma unroll
        for (int t = 0; t < 9; ++t) w[t] = __ldg(wp + t);
        float w2 = 0.f;
#pragma unroll
        for (int t = 0; t < 9; ++t) w2 += w[t] * w[t];
#pragma unroll
        for (int b = 0; b < 8; ++b) {
            const float sm = g_smod[b * 512 + i];
            accs[b] += w2 * g_s2[b * 512 + i];
            float g[3][3];
#pragma unroll
            for (int r = 0; r < 3; ++r)
#pragma unroll
                for (int c = 0; c < 3; ++c) g[r][c] = w[r * 3 + c] * sm;
            // Gg: 4x3
            float q[4][3];
#pragma unroll
            for (int c = 0; c < 3; ++c) {
                q[0][c] = g[0][c];
                q[1][c] = 0.5f * (g[0][c] + g[1][c] + g[2][c]);
                q[2][c] = 0.5f * (g[0][c] - g[1][c] + g[2][c]);
                q[3][c] = g[2][c];
            }
            // (Gg)G^T: 4x4, write
            __half* ub = g_U + ((size_t)(b * 16) * OC + o) * IC + i;
#pragma unroll
            for (int r = 0; r < 4; ++r) {
                float u0 = q[r][0];
                float u1 = 0.5f * (q[r][0] + q[r][1] + q[r][2]);
                float u2 = 0.5f * (q[r][0] - q[r][1] + q[r][2]);
                float u3 = q[r][2];
                ub[(size_t)(r * 4 + 0) * OC * IC] = __float2half_rn(u0);
                ub[(size_t)(r * 4 + 1) * OC * IC] = __float2half_rn(u1);
                ub[(size_t)(r * 4 + 2) * OC * IC] = __float2half_rn(u2);
                ub[(size_t)(r * 4 + 3) * OC * IC] = __float2half_rn(u3);
            }
        }
    }
#pragma unroll
    for (int st = 16; st > 0; st >>= 1)
#pragma unroll
        for (int b = 0; b < 8; ++b)
            accs[b] += __shfl_xor_sync(0xffffffffu, accs[b], st);
    if (lane == 0)
#pragma unroll
        for (int b = 0; b < 8; ++b) red[b][wrp] = accs[b];
    __syncthreads();
    if (tid < 8) {
        float v = 0.f;
#pragma unroll
        for (int w8 = 0; w8 < 8; ++w8) v += red[tid][w8];
        g_sig[tid * 512 + o] = rsqrtf(v * (1.0f / 4608.0f) + 1e-8f);
    }
}

// ---------------------------------------------------------------------------
// K3: V = B^T d B per (b,i,tile), fp16.  d[u][v] = x[2ty-1+u][2tx-1+v] (0-pad)
// B^T rows: r0=d0-d2; r1=d1+d2; r2=d2-d1; r3=d1-d3  (then same along cols)
// ---------------------------------------------------------------------------
__global__ void k_vprep(const float* __restrict__ x) {
    __shared__ float tile[66][68];
    const int i = blockIdx.x, b = blockIdx.y, tid = threadIdx.x;
    const float* xc = x + ((size_t)(b * IC + i) << 12);
    for (int c = tid; c < 66 * 34; c += 256)
        *(float2*)(&tile[0][0] + c * 2) = make_float2(0.f, 0.f);
    __syncthreads();
    for (int c = tid; c < 64 * 16; c += 256) {
        const int r = c >> 4, c4 = (c & 15) * 4;
        float4 v = *(const float4*)(xc + (r << 6) + c4);
        tile[r + 1][c4 + 1] = v.x;
        tile[r + 1][c4 + 2] = v.y;
        tile[r + 1][c4 + 3] = v.z;
        tile[r + 1][c4 + 4] = v.w;
    }
    __syncthreads();
    __half* vb = g_V + ((size_t)(b * 16) * IC + i) * NT;
#pragma unroll 1
    for (int j = 0; j < 4; ++j) {
        const int t = tid * 4 + j;
        const int ty = t >> 5, tx = t & 31;
        float d[4][4];
#pragma unroll
        for (int u = 0; u < 4; ++u)
#pragma unroll
            for (int v = 0; v < 4; ++v) d[u][v] = tile[2 * ty + u][2 * tx + v];
        float r_[4][4];
#pragma unroll
        for (int v = 0; v < 4; ++v) {
            r_[0][v] = d[0][v] - d[2][v];
            r_[1][v] = d[1][v] + d[2][v];
            r_[2][v] = d[2][v] - d[1][v];
            r_[3][v] = d[1][v] - d[3][v];
        }
#pragma unroll
        for (int u = 0; u < 4; ++u) {
            float v0 = r_[u][0] - r_[u][2];
            float v1 = r_[u][1] + r_[u][2];
            float v2 = r_[u][2] - r_[u][1];
            float v3 = r_[u][1] - r_[u][3];
            vb[(size_t)(u * 4 + 0) * IC * NT + t] = __float2half_rn(v0);
            vb[(size_t)(u * 4 + 1) * IC * NT + t] = __float2half_rn(v1);
            vb[(size_t)(u * 4 + 2) * IC * NT + t] = __float2half_rn(v2);
            vb[(size_t)(u * 4 + 3) * IC * NT + t] = __float2half_rn(v3);
        }
    }
}

// ---------------------------------------------------------------------------
// K4: 16 batched GEMMs per (b):  M[xi] = U[xi] (512x512) @ V[xi] (512x1024).
// Persistent over xi: grid (4 mt, 8 nt, 8 b) = 256 CTAs = ONE wave at occ 2.
// BM=128 x BN=128 x BK=32, 5-stage cp.async (proven R15 mainloop).
// 256 global stages: S -> (xi = S>>4, s = S&15).  M stored fp16.
// ---------------------------------------------------------------------------
#define A_ST   10240               // 128 * 80
#define B_ST   8704                // 32 * 272
#define B_OFF  (STG * A_ST)        // 51,200
#define SMEM_TOTAL (B_OFF + STG * B_ST)   // 94,720

__global__ void __launch_bounds__(256, 2)
k_wgemm() {
    extern __shared__ char smem[];
    const uint32_t sb = (uint32_t)__cvta_generic_to_shared(smem);
    const int tid = threadIdx.x, wid = tid >> 5, lane = tid & 31;
    const int mt = blockIdx.x, nt = blockIdx.y, b = blockIdx.z;
    const int o0 = mt * 128, p0 = nt * 128;
    const int wm = (wid >> 1) * 32, wn = (wid & 1) * 64;

    // A: 2 cp16/thread.  row = tid>>1, 32-half chunk half = tid&1
    const int arow = tid >> 1, ac0 = (tid & 1) * 2;
    const uint32_t adst = sb + (uint32_t)(arow * 80 + ac0 * 16);
    // B: 2 cp16/thread.  k-row = tid>>3, 16-half seg = tid&7
    const int kr = tid >> 3, seg = tid & 7;
    const uint32_t bdst = sb + B_OFF + (uint32_t)(kr * 272 + seg * 32);

    auto issue = [&](int S, int buf) {
        const int xi = S >> 4, s = S & 15;
        const __half* ap = g_U +
            ((size_t)(b * 16 + xi) * OC + o0 + arow) * IC + ac0 * 8 + s * 32;
        const uint32_t ad = adst + buf * A_ST;
        cp16(ad, ap);
        cp16(ad + 16, ap + 8);
        const __half* bp = g_V +
            ((size_t)(b * 16 + xi) * IC + s * 32 + kr) * NT + p0 + seg * 16;
        const uint32_t bd = bdst + buf * B_ST;
        cp16(bd, bp);
        cp16(bd + 16, bp + 8);
    };

    const uint32_t a_lane = (uint32_t)((lane & 15) * 80 + (lane >> 4) * 16);
    const uint32_t b_lane = (uint32_t)((((lane & 7) + ((lane >> 3) & 1) * 8) * 136 +
                                       ((lane >> 4) << 3)) * 2);

    float acc[2][8][4];
#pragma unroll
    for (int mi = 0; mi < 2; ++mi)
#pragma unroll
        for (int j = 0; j < 8; ++j)
#pragma unroll
            for (int q = 0; q < 4; ++q) acc[mi][j][q] = 0.f;

    issue(0, 0); cp_commit();
    issue(1, 1); cp_commit();
    issue(2, 2); cp_commit();
    issue(3, 3); cp_commit();

    const int row_l = lane >> 2, col_l = (lane & 3) * 2;
    int ibuf = 4, cbuf = 0;
#pragma unroll 1
    for (int S = 0; S < 256; ++S) {
        cp_wait3();
        __syncthreads();
        if (S + 4 < 256) issue(S + 4, ibuf);
        cp_commit();
        if (++ibuf == STG) ibuf = 0;

        const uint32_t ab = sb + cbuf * A_ST;
        const uint32_t bb = sb + B_OFF + cbuf * B_ST;
        if (++cbuf == STG) cbuf = 0;

        uint32_t af[2][2][4];
#pragma unroll
        for (int mi = 0; mi < 2; ++mi) {
            const uint32_t ad = ab + (uint32_t)((wm + mi * 16) * 80) + a_lane;
            ldsm4(af[mi][0], ad);
            ldsm4(af[mi][1], ad + 32);
        }
#pragma unroll
        for (int n2 = 0; n2 < 4; ++n2) {
#pragma unroll
            for (int f = 0; f < 2; ++f) {
                uint32_t bf[4];
                ldsm4t(bf, bb + (uint32_t)(f * 4352) +
                           (uint32_t)((wn + n2 * 16) * 2) + b_lane);
#pragma unroll
                for (int mi = 0; mi < 2; ++mi)
#pragma unroll
                    for (int nf = 0; nf < 2; ++nf)
                        mma16816(acc[mi][n2 * 2 + nf], af[mi][f], &bf[nf * 2]);
            }
        }

        if ((S & 15) == 15) {          // end of xi: store M fp16, reset acc
            const int xi = S >> 4;
            __half* mb = g_M + ((size_t)(b * 16 + xi) * OC) * NT;
#pragma unroll
            for (int mi = 0; mi < 2; ++mi) {
                const int oa = o0 + wm + mi * 16 + row_l;
                __half* r0 = mb + (size_t)oa * NT + p0 + wn + col_l;
                __half* r1 = mb + (size_t)(oa + 8) * NT + p0 + wn + col_l;
#pragma unroll
                for (int j = 0; j < 8; ++j) {
                    *(__half2*)(r0 + j * 8) =
                        __floats2half2_rn(acc[mi][j][0], acc[mi][j][1]);
                    *(__half2*)(r1 + j * 8) =
                        __floats2half2_rn(acc[mi][j][2], acc[mi][j][3]);
                    acc[mi][j][0] = acc[mi][j][1] = 0.f;
                    acc[mi][j][2] = acc[mi][j][3] = 0.f;
                }
            }
        }
    }
}

// ---------------------------------------------------------------------------
// K5: inverse transform Y = A^T M A + demod + bias.
// A^T = [[1,1,1,0],[0,1,-1,-1]]
// ---------------------------------------------------------------------------
__global__ void k_inverse(const float* __restrict__ b_conv,
                          float* __restrict__ out) {
    const int o = blockIdx.x, b = blockIdx.y, tid = threadIdx.x;
    const float sg = g_sig[b * OC + o];
    const float bi = b_conv[o];
    const __half* mb = g_M + ((size_t)(b * 16) * OC + o) * NT;
    float* ob = out + (((size_t)(b * OC + o)) << 12);
#pragma unroll 1
    for (int j = 0; j < 4; ++j) {
        const int t = tid * 4 + j;
        const int ty = t >> 5, tx = t & 31;
        float m[4][4];
#pragma unroll
        for (int u = 0; u < 4; ++u)
#pragma unroll
            for (int v = 0; v < 4; ++v)
                m[u][v] = __half2float(mb[(size_t)(u * 4 + v) * OC * NT + t]);
        float r0[4], r1[4];
#pragma unroll
        for (int v = 0; v < 4; ++v) {
            r0[v] = m[0][v] + m[1][v] + m[2][v];
            r1[v] = m[1][v] - m[2][v] - m[3][v];
        }
        const float y00 = r0[0] + r0[1] + r0[2];
        const float y01 = r0[1] - r0[2] - r0[3];
        const float y10 = r1[0] + r1[1] + r1[2];
        const float y11 = r1[1] - r1[2] - r1[3];
        float* p = ob + (2 * ty) * 64 + 2 * tx;
        *(float2*)p        = make_float2(y00 * sg + bi, y01 * sg + bi);
        *(float2*)(p + 64) = make_float2(y10 * sg + bi, y11 * sg + bi);
    }
}

// ---------------------------------------------------------------------------
extern "C" void kernel_launch(void* const* d_in, const int* in_sizes, int n_in,
                              void* d_out, int out_size) {
    const float* x      = (const float*)d_in[0];
    const float* latent = (const float*)d_in[1];
    const float* w_lin  = (const float*)d_in[2];
    const float* b_lin  = (const float*)d_in[3];
    const float* w_conv = (const float*)d_in[4];
    const float* b_conv = (const float*)d_in[5];
    float* out = (float*)d_out;

    cudaFuncSetAttribute(k_wgemm, cudaFuncAttributeMaxDynamicSharedMemorySize, SMEM_TOTAL);

    k_style<<<dim3(NB, 64), 256>>>(latent, w_lin, b_lin);
    k_uprep<<<OC, 256>>>(w_conv);
    k_vprep<<<dim3(IC, NB), 256>>>(x);
    k_wgemm<<<dim3(4, 8, NB), 256, SMEM_TOTAL>>>();
    k_inverse<<<dim3(OC, NB), 256>>>(b_conv, out);
}